// round 17
// baseline (speedup 1.0000x reference)
#include <cuda_runtime.h>
#include <cuda_bf16.h>
#include <math.h>
#include <stdint.h>

// Problem constants (fixed by reference)
constexpr int NN  = 100000;
constexpr int EE  = 1600000;
constexpr int FIN = 512;
constexpr int HH  = 128;
constexpr int CC  = 64;

// Packed transposed/split weight buffer segment bases (elements)
constexpr int WOFF_W0  = 0;         // 512x128
constexpr int WOFF_W1  = 65536;     // 128x128
constexpr int WOFF_W2  = 81920;
constexpr int WOFF_FC1 = 98304;
constexpr int WOFF_FC2 = 114688;
constexpr int WOFF_FC3 = 131072;    // 128x64
constexpr int WTOT     = 139264;

// Scratch (device globals: allocation-free rule)
__device__ float g_hA[(size_t)NN * HH];
__device__ float g_hB[(size_t)NN * HH];
__device__ float g_y[(size_t)NN * HH];
__device__ float g_logits[(size_t)NN * CC];
__device__ float g_dinv[NN];
__device__ int   g_rowptr[NN + 1];
__device__ int   g_cursor[NN];
__device__ int   g_csr_src[EE];
__device__ float g_csr_norm[EE];
__device__ int   g_bsum[256];
__device__ __nv_bfloat16 g_wthi[WTOT];
__device__ __nv_bfloat16 g_wtlo[WTOT];

// ---------------------------------------------------------------------------
// PTX helpers (baseline ISA; compiles for compute_103)
// ---------------------------------------------------------------------------
__device__ __forceinline__ uint32_t sptr(const void* p) {
    return (uint32_t)__cvta_generic_to_shared(p);
}
__device__ __forceinline__ void ldm4(uint32_t* r, uint32_t addr) {
    asm volatile("ldmatrix.sync.aligned.m8n8.x4.shared.b16 {%0,%1,%2,%3}, [%4];"
                 : "=r"(r[0]), "=r"(r[1]), "=r"(r[2]), "=r"(r[3]) : "r"(addr));
}
__device__ __forceinline__ void mma16816(float* c, const uint32_t* a, const uint32_t* b) {
    asm volatile(
        "mma.sync.aligned.m16n8k16.row.col.f32.bf16.bf16.f32 "
        "{%0,%1,%2,%3}, {%4,%5,%6,%7}, {%8,%9}, {%0,%1,%2,%3};"
        : "+f"(c[0]), "+f"(c[1]), "+f"(c[2]), "+f"(c[3])
        : "r"(a[0]), "r"(a[1]), "r"(a[2]), "r"(a[3]), "r"(b[0]), "r"(b[1]));
}
__device__ __forceinline__ void cp16(uint32_t saddr, const void* gaddr) {
    asm volatile("cp.async.ca.shared.global [%0], [%1], 16;"
                 :: "r"(saddr), "l"(gaddr) : "memory");
}
__device__ __forceinline__ void cp_commit() {
    asm volatile("cp.async.commit_group;" ::: "memory");
}
__device__ __forceinline__ void cp_wait0() {
    asm volatile("cp.async.wait_group 0;" ::: "memory");
}

// ---------------------------------------------------------------------------
// bf16 3-term split GEMM, software-pipelined (proven R11 version).
// ---------------------------------------------------------------------------
#define APITCH 40   // smem pitch in halves (80B; breaks ldmatrix bank conflicts)

template <int BN_>
__global__ __launch_bounds__(256, 2) void bf16_gemm(
    const float* __restrict__ A,
    const __nv_bfloat16* __restrict__ Bt_hi,
    const __nv_bfloat16* __restrict__ Bt_lo,
    const float* __restrict__ bias, float* __restrict__ C,
    int M, int K, int relu)
{
    constexpr int NF = BN_ / 16;
    constexpr int A_EL  = 128 * APITCH;
    constexpr int B_EL  = BN_ * APITCH;
    constexpr int BUF_EL = 2 * A_EL + 2 * B_EL;
    extern __shared__ __align__(16) __nv_bfloat16 sm[];

    const int tid  = threadIdx.x;
    const int wid  = tid >> 5;
    const int lane = tid & 31;
    const int warp_m = wid & 3;
    const int warp_n = wid >> 2;
    const int blockRow = blockIdx.x * 128;

    float acc[2][NF][4];
#pragma unroll
    for (int i = 0; i < 2; i++)
#pragma unroll
        for (int j = 0; j < NF; j++)
#pragma unroll
            for (int q = 0; q < 4; q++) acc[i][j][q] = 0.f;

    auto A_hi = [&](int b) { return sm + b * BUF_EL; };
    auto A_lo = [&](int b) { return sm + b * BUF_EL + A_EL; };
    auto B_hi = [&](int b) { return sm + b * BUF_EL + 2 * A_EL; };
    auto B_lo = [&](int b) { return sm + b * BUF_EL + 2 * A_EL + B_EL; };

    float4 areg[4];
    auto loadA = [&](int k0) {
#pragma unroll
        for (int p = 0; p < 4; p++) {
            int v = p * 256 + tid;
            int r = v >> 3, cq = (v & 7) * 4;
            int grow = blockRow + r;
            areg[p] = (grow < M)
                ? *(const float4*)(A + (size_t)grow * K + k0 + cq)
                : make_float4(0.f, 0.f, 0.f, 0.f);
        }
    };
    auto storeA = [&](int b) {
        __nv_bfloat16* ah = A_hi(b);
        __nv_bfloat16* al = A_lo(b);
#pragma unroll
        for (int p = 0; p < 4; p++) {
            int v = p * 256 + tid;
            int r = v >> 3, cq = (v & 7) * 4;
            float4 x = areg[p];
            __nv_bfloat16 h0 = __float2bfloat16_rn(x.x);
            __nv_bfloat16 h1 = __float2bfloat16_rn(x.y);
            __nv_bfloat16 h2 = __float2bfloat16_rn(x.z);
            __nv_bfloat16 h3 = __float2bfloat16_rn(x.w);
            __nv_bfloat16 l0 = __float2bfloat16_rn(x.x - __bfloat162float(h0));
            __nv_bfloat16 l1 = __float2bfloat16_rn(x.y - __bfloat162float(h1));
            __nv_bfloat16 l2 = __float2bfloat16_rn(x.z - __bfloat162float(h2));
            __nv_bfloat16 l3 = __float2bfloat16_rn(x.w - __bfloat162float(h3));
            *(__nv_bfloat162*)(ah + r * APITCH + cq)     = __halves2bfloat162(h0, h1);
            *(__nv_bfloat162*)(ah + r * APITCH + cq + 2) = __halves2bfloat162(h2, h3);
            *(__nv_bfloat162*)(al + r * APITCH + cq)     = __halves2bfloat162(l0, l1);
            *(__nv_bfloat162*)(al + r * APITCH + cq + 2) = __halves2bfloat162(l2, l3);
        }
    };
    auto loadB = [&](int k0, int b) {
        int c = tid;
        if (BN_ == 64 && c >= 128) return;
        int n = c >> 1, kc = (c & 1) * 16;
        const __nv_bfloat16* gh = Bt_hi + (size_t)n * K + k0 + kc;
        const __nv_bfloat16* gl = Bt_lo + (size_t)n * K + k0 + kc;
        uint32_t sh = sptr(B_hi(b) + n * APITCH + kc);
        uint32_t sl = sptr(B_lo(b) + n * APITCH + kc);
        cp16(sh,      gh);
        cp16(sh + 16, gh + 8);
        cp16(sl,      gl);
        cp16(sl + 16, gl + 8);
    };
    auto compute = [&](int b) {
#pragma unroll
        for (int kk = 0; kk < 32; kk += 16) {
            uint32_t aH[2][4], aL[2][4];
            {
                int row = warp_m * 32 + (lane & 15);
                int col = kk + ((lane >> 4) << 3);
#pragma unroll
                for (int fm = 0; fm < 2; fm++) {
                    ldm4(aH[fm], sptr(A_hi(b) + (row + fm * 16) * APITCH + col));
                    ldm4(aL[fm], sptr(A_lo(b) + (row + fm * 16) * APITCH + col));
                }
            }
            uint32_t bH[NF][2], bL[NF][2];
            {
                int rbase = warp_n * (NF * 8) + (lane & 7) + ((lane >> 4) << 3);
                int col = kk + ((lane >> 3) & 1) * 8;
#pragma unroll
                for (int fp = 0; fp < NF / 2; fp++) {
                    uint32_t t[4];
                    ldm4(t, sptr(B_hi(b) + (rbase + fp * 16) * APITCH + col));
                    bH[fp * 2][0] = t[0]; bH[fp * 2][1] = t[1];
                    bH[fp * 2 + 1][0] = t[2]; bH[fp * 2 + 1][1] = t[3];
                    ldm4(t, sptr(B_lo(b) + (rbase + fp * 16) * APITCH + col));
                    bL[fp * 2][0] = t[0]; bL[fp * 2][1] = t[1];
                    bL[fp * 2 + 1][0] = t[2]; bL[fp * 2 + 1][1] = t[3];
                }
            }
#pragma unroll
            for (int fm = 0; fm < 2; fm++)
#pragma unroll
                for (int fn = 0; fn < NF; fn++) {
                    mma16816(acc[fm][fn], aH[fm], bH[fn]);
                    mma16816(acc[fm][fn], aH[fm], bL[fn]);
                    mma16816(acc[fm][fn], aL[fm], bH[fn]);
                }
        }
    };

    const int KB = K >> 5;
    loadA(0);
    loadB(0, 0);
    cp_commit();
    storeA(0);
    cp_wait0();
    __syncthreads();

    int buf = 0;
    for (int kb = 0; kb < KB; kb++) {
        const bool has_next = (kb + 1 < KB);
        if (has_next) {
            loadA((kb + 1) * 32);
            loadB((kb + 1) * 32, buf ^ 1);
            cp_commit();
        }
        compute(buf);
        if (has_next) {
            storeA(buf ^ 1);
            cp_wait0();
            __syncthreads();
        }
        buf ^= 1;
    }

#pragma unroll
    for (int fm = 0; fm < 2; fm++) {
#pragma unroll
        for (int fn = 0; fn < NF; fn++) {
            int gn = warp_n * (NF * 8) + fn * 8 + (lane & 3) * 2;
            float2 bv = *(const float2*)(bias + gn);
            int gm0 = blockRow + warp_m * 32 + fm * 16 + (lane >> 2);
            float2 v0, v1;
            v0.x = acc[fm][fn][0] + bv.x;
            v0.y = acc[fm][fn][1] + bv.y;
            v1.x = acc[fm][fn][2] + bv.x;
            v1.y = acc[fm][fn][3] + bv.y;
            if (relu) {
                v0.x = fmaxf(v0.x, 0.f); v0.y = fmaxf(v0.y, 0.f);
                v1.x = fmaxf(v1.x, 0.f); v1.y = fmaxf(v1.y, 0.f);
            }
            if (gm0 < M)     *(float2*)(C + (size_t)gm0 * BN_ + gn) = v0;
            if (gm0 + 8 < M) *(float2*)(C + (size_t)(gm0 + 8) * BN_ + gn) = v1;
        }
    }
}

// ---------------------------------------------------------------------------
// All-weights transpose + bf16 hi/lo split into packed buffer.
// ---------------------------------------------------------------------------
__global__ void wsplit_all(const float* __restrict__ W0, const float* __restrict__ W1,
                           const float* __restrict__ W2, const float* __restrict__ f1,
                           const float* __restrict__ f2, const float* __restrict__ f3,
                           __nv_bfloat16* __restrict__ hi, __nv_bfloat16* __restrict__ lo)
{
    int i = blockIdx.x * blockDim.x + threadIdx.x;
    if (i >= WTOT) return;
    const float* w; int K, Nn, base;
    if      (i < WOFF_W1)  { w = W0; K = FIN; Nn = HH; base = WOFF_W0;  }
    else if (i < WOFF_W2)  { w = W1; K = HH;  Nn = HH; base = WOFF_W1;  }
    else if (i < WOFF_FC1) { w = W2; K = HH;  Nn = HH; base = WOFF_W2;  }
    else if (i < WOFF_FC2) { w = f1; K = HH;  Nn = HH; base = WOFF_FC1; }
    else if (i < WOFF_FC3) { w = f2; K = HH;  Nn = HH; base = WOFF_FC2; }
    else                   { w = f3; K = HH;  Nn = CC; base = WOFF_FC3; }
    int j = i - base;
    int k = j / Nn, n = j % Nn;
    float v = w[j];
    __nv_bfloat16 h = __float2bfloat16_rn(v);
    hi[base + (size_t)n * K + k] = h;
    lo[base + (size_t)n * K + k] = __float2bfloat16_rn(v - __bfloat162float(h));
}

// ---------------------------------------------------------------------------
// CSR build: histogram -> scan -> fill (edges sorted by dst)
// ---------------------------------------------------------------------------
__global__ void deg_count(const int* __restrict__ dst, int* __restrict__ rowptr, int E)
{
    int e = blockIdx.x * blockDim.x + threadIdx.x;
    if (e < E) atomicAdd(&rowptr[dst[e] + 1], 1);
}

__global__ __launch_bounds__(1024) void scan1(int* __restrict__ arr,
                                              int* __restrict__ bsum, int n)
{
    __shared__ int s[1024];
    int tid = threadIdx.x;
    int i = blockIdx.x * 1024 + tid;
    int v = (i < n) ? arr[i] : 0;
    s[tid] = v;
    __syncthreads();
#pragma unroll
    for (int off = 1; off < 1024; off <<= 1) {
        int t = (tid >= off) ? s[tid - off] : 0;
        __syncthreads();
        s[tid] += t;
        __syncthreads();
    }
    if (i < n) arr[i] = s[tid];
    if (tid == 1023) bsum[blockIdx.x] = s[1023];
}

__global__ void scan2(int* __restrict__ bsum, int nb)
{
    if (threadIdx.x == 0 && blockIdx.x == 0) {
        int run = 0;
        for (int i = 0; i < nb; i++) { int v = bsum[i]; bsum[i] = run; run += v; }
    }
}

__global__ __launch_bounds__(1024) void scan3(int* __restrict__ arr,
                                              const int* __restrict__ bsum, int n)
{
    int i = blockIdx.x * 1024 + threadIdx.x;
    if (i < n) arr[i] += bsum[blockIdx.x];
}

__global__ void fin_deg(const int* __restrict__ rowptr, float* __restrict__ dinv,
                        int* __restrict__ cursor, int n)
{
    int i = blockIdx.x * blockDim.x + threadIdx.x;
    if (i < n) {
        int beg = rowptr[i];
        int deg = rowptr[i + 1] - beg;
        dinv[i] = rsqrtf((float)deg + 1.0f);
        cursor[i] = beg;
    }
}

__global__ void fill_csr(const int* __restrict__ src, const int* __restrict__ dst,
                         const float* __restrict__ dinv, int* __restrict__ cursor,
                         int* __restrict__ csr_src, float* __restrict__ csr_norm, int E)
{
    int e = blockIdx.x * blockDim.x + threadIdx.x;
    if (e >= E) return;
    int s = src[e];
    int d = dst[e];
    int pos = atomicAdd(&cursor[d], 1);
    csr_src[pos] = s;
    csr_norm[pos] = dinv[s] * dinv[d];
}

// ---------------------------------------------------------------------------
// Gather aggregation over node range [base, base+count):
//   y[node] = relu(sum_e h[src_e]*norm_e + h[node]*dinv^2)
// ---------------------------------------------------------------------------
__global__ __launch_bounds__(256) void gather_conv(
    const float* __restrict__ h, const int* __restrict__ csr_src,
    const float* __restrict__ csr_norm, const int* __restrict__ rowptr,
    const float* __restrict__ dinv, float* __restrict__ y,
    int base, int count)
{
    int idx = blockIdx.x * 8 + (threadIdx.x >> 5);
    if (idx >= count) return;
    int node = base + idx;
    int lane = threadIdx.x & 31;

    int beg = rowptr[node];
    int end = rowptr[node + 1];
    float di = dinv[node];
    float w = di * di;

    const float* hl = h + lane * 4;
    float4 self = *(const float4*)(hl + (size_t)node * HH);
    float4 acc;
    acc.x = self.x * w; acc.y = self.y * w;
    acc.z = self.z * w; acc.w = self.w * w;

    int e = beg;
    for (; e + 3 < end; e += 4) {
        int s0 = __ldg(csr_src + e);
        int s1 = __ldg(csr_src + e + 1);
        int s2 = __ldg(csr_src + e + 2);
        int s3 = __ldg(csr_src + e + 3);
        float n0 = __ldg(csr_norm + e);
        float n1 = __ldg(csr_norm + e + 1);
        float n2 = __ldg(csr_norm + e + 2);
        float n3 = __ldg(csr_norm + e + 3);
        float4 v0 = *(const float4*)(hl + (size_t)s0 * HH);
        float4 v1 = *(const float4*)(hl + (size_t)s1 * HH);
        float4 v2 = *(const float4*)(hl + (size_t)s2 * HH);
        float4 v3 = *(const float4*)(hl + (size_t)s3 * HH);
        acc.x = fmaf(v0.x, n0, acc.x); acc.y = fmaf(v0.y, n0, acc.y);
        acc.z = fmaf(v0.z, n0, acc.z); acc.w = fmaf(v0.w, n0, acc.w);
        acc.x = fmaf(v1.x, n1, acc.x); acc.y = fmaf(v1.y, n1, acc.y);
        acc.z = fmaf(v1.z, n1, acc.z); acc.w = fmaf(v1.w, n1, acc.w);
        acc.x = fmaf(v2.x, n2, acc.x); acc.y = fmaf(v2.y, n2, acc.y);
        acc.z = fmaf(v2.z, n2, acc.z); acc.w = fmaf(v2.w, n2, acc.w);
        acc.x = fmaf(v3.x, n3, acc.x); acc.y = fmaf(v3.y, n3, acc.y);
        acc.z = fmaf(v3.z, n3, acc.z); acc.w = fmaf(v3.w, n3, acc.w);
    }
    for (; e < end; e++) {
        int s = __ldg(csr_src + e);
        float nm = __ldg(csr_norm + e);
        float4 v = *(const float4*)(hl + (size_t)s * HH);
        acc.x = fmaf(v.x, nm, acc.x);
        acc.y = fmaf(v.y, nm, acc.y);
        acc.z = fmaf(v.z, nm, acc.z);
        acc.w = fmaf(v.w, nm, acc.w);
    }
    acc.x = fmaxf(acc.x, 0.f);
    acc.y = fmaxf(acc.y, 0.f);
    acc.z = fmaxf(acc.z, 0.f);
    acc.w = fmaxf(acc.w, 0.f);
    *(float4*)(y + (size_t)node * HH + lane * 4) = acc;
}

// ---------------------------------------------------------------------------
// log_softmax over C=64 classes; 1 warp per row, 2 classes per lane.
// ---------------------------------------------------------------------------
__global__ void log_softmax_k(const float* __restrict__ logits, float* __restrict__ out, int N)
{
    int row = blockIdx.x * blockDim.y + threadIdx.y;
    if (row >= N) return;
    int lane = threadIdx.x;
    const float* lr = logits + (size_t)row * CC;
    float v0 = lr[lane], v1 = lr[lane + 32];
    float m = fmaxf(v0, v1);
#pragma unroll
    for (int o = 16; o; o >>= 1) m = fmaxf(m, __shfl_xor_sync(0xffffffffu, m, o));
    float s = expf(v0 - m) + expf(v1 - m);
#pragma unroll
    for (int o = 16; o; o >>= 1) s += __shfl_xor_sync(0xffffffffu, s, o);
    float ls = m + logf(s);
    float* orow = out + (size_t)row * CC;
    orow[lane] = v0 - ls;
    orow[lane + 32] = v1 - ls;
}

// ---------------------------------------------------------------------------
// Launch — CSR overlapped with conv0; gather/GEMM chunk-pipelined across two
// streams with ping-pong h buffers (gemm never writes the buffer gathers read).
// ---------------------------------------------------------------------------
extern "C" void kernel_launch(void* const* d_in, const int* in_sizes, int n_in,
                              void* d_out, int out_size)
{
    const float* x     = (const float*)d_in[0];
    const int*   ei    = (const int*)d_in[1];
    const float* W0    = (const float*)d_in[2];
    const float* b0    = (const float*)d_in[3];
    const float* W1    = (const float*)d_in[4];
    const float* b1    = (const float*)d_in[5];
    const float* W2    = (const float*)d_in[6];
    const float* b2    = (const float*)d_in[7];
    const float* fc1_w = (const float*)d_in[8];
    const float* fc1_b = (const float*)d_in[9];
    const float* fc2_w = (const float*)d_in[10];
    const float* fc2_b = (const float*)d_in[11];
    const float* fc3_w = (const float*)d_in[12];
    const float* fc3_b = (const float*)d_in[13];

    const int N = in_sizes[0] / FIN;   // 100000
    const int E = in_sizes[1] / 2;     // 1600000
    const int* src = ei;
    const int* dst = ei + E;

    float *hA_, *hB_, *y_, *logits_, *dinv_, *csr_norm_;
    int *rowptr_, *cursor_, *csr_src_, *bsum_;
    __nv_bfloat16 *wthi_, *wtlo_;
    cudaGetSymbolAddress((void**)&hA_,      g_hA);
    cudaGetSymbolAddress((void**)&hB_,      g_hB);
    cudaGetSymbolAddress((void**)&y_,       g_y);
    cudaGetSymbolAddress((void**)&logits_,  g_logits);
    cudaGetSymbolAddress((void**)&dinv_,    g_dinv);
    cudaGetSymbolAddress((void**)&rowptr_,  g_rowptr);
    cudaGetSymbolAddress((void**)&cursor_,  g_cursor);
    cudaGetSymbolAddress((void**)&csr_src_, g_csr_src);
    cudaGetSymbolAddress((void**)&csr_norm_,g_csr_norm);
    cudaGetSymbolAddress((void**)&bsum_,    g_bsum);
    cudaGetSymbolAddress((void**)&wthi_,    g_wthi);
    cudaGetSymbolAddress((void**)&wtlo_,    g_wtlo);

    constexpr int SMEM128 = (2 * (2 * 128 * APITCH + 2 * 128 * APITCH)) * 2; // 81920
    constexpr int SMEM64  = (2 * (2 * 128 * APITCH + 2 * 64  * APITCH)) * 2; // 61440
    cudaFuncSetAttribute(bf16_gemm<128>, cudaFuncAttributeMaxDynamicSharedMemorySize, SMEM128);
    cudaFuncSetAttribute(bf16_gemm<64>,  cudaFuncAttributeMaxDynamicSharedMemorySize, SMEM64);

    // One-time stream/event creation (host-side; no device memory involved)
    static cudaStream_t s2 = nullptr;
    static cudaEvent_t ev_fork = nullptr, ev_csr = nullptr;
    static cudaEvent_t evA[4] = {}, evB[4] = {};
    if (s2 == nullptr) {
        cudaStreamCreateWithFlags(&s2, cudaStreamNonBlocking);
        cudaEventCreateWithFlags(&ev_fork, cudaEventDisableTiming);
        cudaEventCreateWithFlags(&ev_csr,  cudaEventDisableTiming);
        for (int i = 0; i < 4; i++) {
            cudaEventCreateWithFlags(&evA[i], cudaEventDisableTiming);
            cudaEventCreateWithFlags(&evB[i], cudaEventDisableTiming);
        }
    }

    const int T = 256;
    const int np1 = N + 1;
    const int nb = (np1 + 1023) / 1024;

    // node chunks (128-aligned split)
    const int M0 = ((N / 2 + 127) / 128) * 128;   // 50048
    const int M1 = N - M0;                        // 49952
    const int gb0 = (M0 + 127) / 128;
    const int gb1 = (M1 + 127) / 128;
    const int gth0 = (M0 + 7) / 8;
    const int gth1 = (M1 + 7) / 8;
    const size_t off1_h = (size_t)M0 * HH;

    // ---- fork: CSR build on s2; weight prep + conv0 GEMM on main ----
    cudaEventRecord(ev_fork, 0);
    cudaStreamWaitEvent(s2, ev_fork, 0);

    cudaMemsetAsync(rowptr_, 0, (size_t)np1 * sizeof(int), s2);
    deg_count<<<(E + T - 1) / T, T, 0, s2>>>(dst, rowptr_, E);
    scan1<<<nb, 1024, 0, s2>>>(rowptr_, bsum_, np1);
    scan2<<<1, 32, 0, s2>>>(bsum_, nb);
    scan3<<<nb, 1024, 0, s2>>>(rowptr_, bsum_, np1);
    fin_deg<<<(N + T - 1) / T, T, 0, s2>>>(rowptr_, dinv_, cursor_, N);
    fill_csr<<<(E + T - 1) / T, T, 0, s2>>>(src, dst, dinv_, cursor_,
                                            csr_src_, csr_norm_, E);
    cudaEventRecord(ev_csr, s2);

    wsplit_all<<<(WTOT + T - 1) / T, T>>>(W0, W1, W2, fc1_w, fc2_w, fc3_w, wthi_, wtlo_);
    bf16_gemm<128><<<(N + 127) / 128, T, SMEM128>>>(x, wthi_ + WOFF_W0, wtlo_ + WOFF_W0,
                                                    b0, hA_, N, FIN, 0);
    cudaStreamWaitEvent(0, ev_csr, 0);

    // ---- conv boundaries 1..2 (ping-pong hA <-> hB) ----
    // b=0: gather(hA->y), gemm(y->hB).  b=1: gather(hB->y), gemm(y->hA).
    const __nv_bfloat16* whi[2] = { wthi_ + WOFF_W1, wthi_ + WOFF_W2 };
    const __nv_bfloat16* wlo[2] = { wtlo_ + WOFF_W1, wtlo_ + WOFF_W2 };
    const float* bb[2] = { b1, b2 };
    float* hin[2]  = { hA_, hB_ };
    float* hout[2] = { hB_, hA_ };

    for (int b = 0; b < 2; b++) {
        if (b > 0) cudaStreamWaitEvent(0, evB[b - 1], 0);
        gather_conv<<<gth0, T>>>(hin[b], csr_src_, csr_norm_, rowptr_, dinv_, y_, 0, M0);
        cudaEventRecord(evA[b], 0);
        bf16_gemm<128><<<gb0, T, SMEM128>>>(y_, whi[b], wlo[b], bb[b], hout[b], M0, HH, 0);

        cudaStreamWaitEvent(s2, evA[b], 0);
        gather_conv<<<gth1, T, 0, s2>>>(hin[b], csr_src_, csr_norm_, rowptr_, dinv_, y_, M0, M1);
        bf16_gemm<128><<<gb1, T, SMEM128, s2>>>(y_ + off1_h, whi[b], wlo[b], bb[b],
                                                hout[b] + off1_h, M1, HH, 0);
        cudaEventRecord(evB[b], s2);
    }

    // ---- boundary 3 (conv2 -> MLP): gather(hA->y); per-chunk fc chains ----
    // chunk chain: fc1(y->hB), fc2(hB->y), fc3(y->logits), softmax(logits->out)
    cudaStreamWaitEvent(0, evB[1], 0);
    gather_conv<<<gth0, T>>>(hA_, csr_src_, csr_norm_, rowptr_, dinv_, y_, 0, M0);
    cudaEventRecord(evA[2], 0);
    bf16_gemm<128><<<gb0, T, SMEM128>>>(y_, wthi_ + WOFF_FC1, wtlo_ + WOFF_FC1, fc1_b, hB_, M0, HH, 1);
    bf16_gemm<128><<<gb0, T, SMEM128>>>(hB_, wthi_ + WOFF_FC2, wtlo_ + WOFF_FC2, fc2_b, y_, M0, HH, 1);
    bf16_gemm<64><<<gb0, T, SMEM64>>>(y_, wthi_ + WOFF_FC3, wtlo_ + WOFF_FC3, fc3_b, logits_, M0, HH, 0);
    {
        dim3 ls_block(32, 8);
        log_softmax_k<<<(M0 + 7) / 8, ls_block>>>(logits_, (float*)d_out, M0);
    }

    cudaStreamWaitEvent(s2, evA[2], 0);
    gather_conv<<<gth1, T, 0, s2>>>(hA_, csr_src_, csr_norm_, rowptr_, dinv_, y_, M0, M1);
    bf16_gemm<128><<<gb1, T, SMEM128, s2>>>(y_ + off1_h, wthi_ + WOFF_FC1, wtlo_ + WOFF_FC1,
                                            fc1_b, hB_ + off1_h, M1, HH, 1);
    bf16_gemm<128><<<gb1, T, SMEM128, s2>>>(hB_ + off1_h, wthi_ + WOFF_FC2, wtlo_ + WOFF_FC2,
                                            fc2_b, y_ + off1_h, M1, HH, 1);
    bf16_gemm<64><<<gb1, T, SMEM64, s2>>>(y_ + off1_h, wthi_ + WOFF_FC3, wtlo_ + WOFF_FC3,
                                          fc3_b, logits_ + (size_t)M0 * CC, M1, HH, 0);
    {
        dim3 ls_block(32, 8);
        log_softmax_k<<<(M1 + 7) / 8, ls_block, 0, s2>>>(logits_ + (size_t)M0 * CC,
                                                         (float*)d_out + (size_t)M0 * CC, M1);
    }
    cudaEventRecord(evB[2], s2);

    // ---- join everything back to the capture stream ----
    cudaStreamWaitEvent(0, evB[2], 0);
}